// round 3
// baseline (speedup 1.0000x reference)
#include <cuda_runtime.h>
#include <math.h>

#define BATCH 2
#define DIM   48
#define HEADS 8
#define CPH   6
#define HH    384
#define WW    384
#define NPIX  (HH*WW)

// ---------------- scratch ----------------
__device__ float g_pwq [BATCH*DIM*NPIX];      // 56.6 MB
__device__ float g_pwkv[BATCH*2*DIM*NPIX];    // 113 MB (k: ch 0..47, v: ch 48..95)
__device__ float g_acc [BATCH*HEADS*48];      // 36 Gram + 6 |q|^2 + 6 |k|^2
__device__ float g_meff[BATCH*DIM*DIM];

// ---------------- packed f32x2 ----------------
__device__ __forceinline__ unsigned long long pk2(float lo, float hi){
    unsigned long long r;
    asm("mov.b64 %0, {%1,%2};" : "=l"(r) : "f"(lo), "f"(hi));
    return r;
}
__device__ __forceinline__ void fma2(unsigned long long &d,
                                     unsigned long long a,
                                     unsigned long long b){
    asm("fma.rn.f32x2 %0, %1, %2, %3;" : "=l"(d) : "l"(a), "l"(b), "l"(d));
}
__device__ __forceinline__ float2 unpk(unsigned long long v){
    float lo, hi;
    asm("mov.b64 {%0,%1}, %2;" : "=f"(lo), "=f"(hi) : "l"(v));
    return make_float2(lo, hi);
}

__device__ __forceinline__ void row3(float* r, const float* rowp, int x, int xl, int xr,
                                     bool xm, bool xp, bool yok){
    r[0] = (yok && xm) ? __ldg(rowp + xl) : 0.f;
    r[1] =  yok        ? __ldg(rowp + x ) : 0.f;
    r[2] = (yok && xp) ? __ldg(rowp + xr) : 0.f;
}

#define CONV9(s, w, a, b_, c) \
    s = w[0]*a[0]+w[1]*a[1]+w[2]*a[2] \
      + w[3]*b_[0]+w[4]*b_[1]+w[5]*b_[2] \
      + w[6]*c[0]+w[7]*c[1]+w[8]*c[2];

// ---------------- kernels ----------------
__global__ void zero_acc_kernel(){
    int t = blockIdx.x*blockDim.x + threadIdx.x;
    if (t < BATCH*HEADS*48) g_acc[t] = 0.f;
}

// 1x1 conv as GEMM: 48 oc, 256 px/block, input tile staged in smem (read once).
// 8 warps x 6 oc, each thread 8 px via FFMA2.
__global__ __launch_bounds__(256, 2) void pw8_kernel(const float* __restrict__ in,
                                                     const float* __restrict__ W,
                                                     float* __restrict__ out,
                                                     int inBC, int outBC){
    extern __shared__ char smraw[];
    unsigned long long* ws = reinterpret_cast<unsigned long long*>(smraw);   // 48*48 u64
    float* xs = reinterpret_cast<float*>(smraw + DIM*DIM*8);                 // 48*256 f32

    const int b = blockIdx.y;
    for (int t = threadIdx.x; t < DIM*DIM; t += 256){
        float w = W[t];
        ws[t] = pk2(w, w);
    }
    const int base = blockIdx.x*256;
    const float* inp = in + (size_t)b*inBC*NPIX + base;
    // stage input tile: 48 ch x 64 float4, each element read exactly once
    for (int e = threadIdx.x; e < DIM*64; e += 256){
        int c = e >> 6, q = e & 63;
        float4 v = *reinterpret_cast<const float4*>(inp + (size_t)c*NPIX + q*4);
        *reinterpret_cast<float4*>(xs + c*256 + q*4) = v;
    }
    __syncthreads();

    const int tid = threadIdx.x;
    const int pxq = tid & 31;
    const int ocg = tid >> 5;

    unsigned long long acc[CPH][4];
    #pragma unroll
    for (int j = 0; j < CPH; j++){
        acc[j][0]=0ull; acc[j][1]=0ull; acc[j][2]=0ull; acc[j][3]=0ull;
    }

    #pragma unroll 4
    for (int ic = 0; ic < DIM; ic++){
        const float4* xp = reinterpret_cast<const float4*>(xs + ic*256 + pxq*8);
        float4 xa = xp[0];
        float4 xb = xp[1];
        unsigned long long a01 = pk2(xa.x, xa.y), a23 = pk2(xa.z, xa.w);
        unsigned long long b01 = pk2(xb.x, xb.y), b23 = pk2(xb.z, xb.w);
        #pragma unroll
        for (int j = 0; j < CPH; j++){
            unsigned long long w = ws[(ocg*CPH + j)*DIM + ic];
            fma2(acc[j][0], a01, w);
            fma2(acc[j][1], a23, w);
            fma2(acc[j][2], b01, w);
            fma2(acc[j][3], b23, w);
        }
    }

    float* op = out + (size_t)b*outBC*NPIX + base + pxq*8;
    #pragma unroll
    for (int j = 0; j < CPH; j++){
        float* o = op + (size_t)(ocg*CPH + j)*NPIX;
        float2 l0 = unpk(acc[j][0]), h0 = unpk(acc[j][1]);
        float2 l1 = unpk(acc[j][2]), h1 = unpk(acc[j][3]);
        *reinterpret_cast<float4*>(o)     = make_float4(l0.x, l0.y, h0.x, h0.y);
        *reinterpret_cast<float4*>(o + 4) = make_float4(l1.x, l1.y, h1.x, h1.y);
    }
}

// q,k depthwise 3x3 + Gram/norm reduction. One head per warp over a 32x8 strip.
// k split into 2 groups of 3 channels; Gram part reduced per group (reg pressure < 100).
__global__ __launch_bounds__(256, 2) void qk_gram_kernel(const float* __restrict__ Wq2,
                                                         const float* __restrict__ Wkv2){
    __shared__ float wq[CPH*9], wk[CPH*9];
    __shared__ float accs[48];
    const int tid = threadIdx.x;
    const int bh  = blockIdx.z;
    const int b   = bh >> 3, h = bh & 7;
    if (tid < CPH*9){
        int c6 = tid/9, t = tid%9;
        wq[tid] = Wq2 [(h*CPH + c6)*27 + 9 + t];
        wk[tid] = Wkv2[(h*CPH + c6)*27 + 9 + t];
    }
    if (tid < 48) accs[tid] = 0.f;
    __syncthreads();

    const int lane = tid & 31;
    const int w    = tid >> 5;
    const int x    = blockIdx.x*32 + lane;
    const int yb   = blockIdx.y*64 + w*8;
    const int  xl = max(x-1, 0), xr = min(x+1, WW-1);
    const bool xm = (x > 0),     xp = (x < WW-1);

    const float* qbase = g_pwq  + (size_t)b*DIM*NPIX   + (size_t)h*CPH*NPIX;
    const float* kbase = g_pwkv + (size_t)b*2*DIM*NPIX + (size_t)h*CPH*NPIX;

    #pragma unroll
    for (int g = 0; g < 2; g++){
        float ka[3][8];
        float kn[3];
        // ---- k channels of this group ----
        #pragma unroll
        for (int c3 = 0; c3 < 3; c3++){
            int c6 = g*3 + c3;
            const float* p = kbase + (size_t)c6*NPIX;
            float wr[9];
            #pragma unroll
            for (int t = 0; t < 9; t++) wr[t] = wk[c6*9 + t];
            float r0[3], r1[3], r2[3];
            { bool yok = (yb-1 >= 0); row3(r0, p + (yok ? (yb-1) : 0)*WW, x, xl, xr, xm, xp, yok); }
            row3(r1, p + yb*WW, x, xl, xr, xm, xp, true);
            float nrm = 0.f;
            #pragma unroll
            for (int i = 0; i < 8; i++){
                int yy = yb + i + 1; bool yok = (yy < HH);
                row3(r2, p + (yok ? yy : 0)*WW, x, xl, xr, xm, xp, yok);
                float s; CONV9(s, wr, r0, r1, r2);
                ka[c3][i] = s; nrm += s*s;
                r0[0]=r1[0]; r0[1]=r1[1]; r0[2]=r1[2];
                r1[0]=r2[0]; r1[1]=r2[1]; r1[2]=r2[2];
            }
            kn[c3] = nrm;
        }

        float Gp[CPH*3];
        #pragma unroll
        for (int i = 0; i < CPH*3; i++) Gp[i] = 0.f;
        float qn[CPH];

        // ---- all q channels, Gram vs this k group ----
        #pragma unroll
        for (int c6 = 0; c6 < CPH; c6++){
            const float* p = qbase + (size_t)c6*NPIX;
            float wr[9];
            #pragma unroll
            for (int t = 0; t < 9; t++) wr[t] = wq[c6*9 + t];
            float r0[3], r1[3], r2[3];
            { bool yok = (yb-1 >= 0); row3(r0, p + (yok ? (yb-1) : 0)*WW, x, xl, xr, xm, xp, yok); }
            row3(r1, p + yb*WW, x, xl, xr, xm, xp, true);
            float nrm = 0.f;
            #pragma unroll
            for (int i = 0; i < 8; i++){
                int yy = yb + i + 1; bool yok = (yy < HH);
                row3(r2, p + (yok ? yy : 0)*WW, x, xl, xr, xm, xp, yok);
                float s; CONV9(s, wr, r0, r1, r2);
                nrm += s*s;
                #pragma unroll
                for (int d3 = 0; d3 < 3; d3++)
                    Gp[c6*3 + d3] += s * ka[d3][i];
                r0[0]=r1[0]; r0[1]=r1[1]; r0[2]=r1[2];
                r1[0]=r2[0]; r1[1]=r2[1]; r1[2]=r2[2];
            }
            qn[c6] = nrm;
        }

        // ---- per-group reduce -> smem ----
        #pragma unroll
        for (int j = 0; j < CPH*3; j++){
            float v = Gp[j];
            #pragma unroll
            for (int o = 16; o; o >>= 1) v += __shfl_xor_sync(0xffffffffu, v, o);
            int c6 = j/3, d3 = j%3;
            if (lane == 0) atomicAdd(&accs[c6*CPH + g*3 + d3], v);
        }
        #pragma unroll
        for (int j = 0; j < 3; j++){
            float u = kn[j];
            #pragma unroll
            for (int o = 16; o; o >>= 1) u += __shfl_xor_sync(0xffffffffu, u, o);
            if (lane == 0) atomicAdd(&accs[42 + g*3 + j], u);
        }
        if (g == 0){
            #pragma unroll
            for (int j = 0; j < CPH; j++){
                float v = qn[j];
                #pragma unroll
                for (int o = 16; o; o >>= 1) v += __shfl_xor_sync(0xffffffffu, v, o);
                if (lane == 0) atomicAdd(&accs[36 + j], v);
            }
        }
    }
    __syncthreads();
    if (tid < 48) atomicAdd(&g_acc[(b*HEADS + h)*48 + tid], accs[tid]);
}

// softmax + fold Wout -> Meff[b] (48x48)
__global__ void attn_kernel(const float* __restrict__ Wout,
                            const float* __restrict__ temp){
    __shared__ float attn_s[BATCH*HEADS*36];
    int t = threadIdx.x;
    if (t < BATCH*HEADS*CPH){
        int b  = t/(HEADS*CPH);
        int h  = (t/CPH)%HEADS;
        int c6 = t%CPH;
        const float* a = g_acc + (b*HEADS + h)*48;
        float qnorm = fmaxf(sqrtf(a[36 + c6]), 1e-12f);
        float s[CPH];
        float mx = -1e30f;
        #pragma unroll
        for (int d6 = 0; d6 < CPH; d6++){
            float knorm = fmaxf(sqrtf(a[42 + d6]), 1e-12f);
            float v = a[c6*CPH + d6] / (qnorm*knorm) * temp[h];
            s[d6] = v; mx = fmaxf(mx, v);
        }
        float sum = 0.f;
        #pragma unroll
        for (int d6 = 0; d6 < CPH; d6++){ s[d6] = expf(s[d6]-mx); sum += s[d6]; }
        float inv = 1.f/sum;
        #pragma unroll
        for (int d6 = 0; d6 < CPH; d6++)
            attn_s[(b*HEADS + h)*36 + c6*CPH + d6] = s[d6]*inv;
    }
    __syncthreads();
    for (int e = t; e < BATCH*DIM*DIM; e += blockDim.x){
        int b = e/(DIM*DIM), rem = e%(DIM*DIM), o = rem/DIM, d = rem%DIM;
        int h = d/CPH, d6 = d%CPH;
        float s = 0.f;
        #pragma unroll
        for (int c6 = 0; c6 < CPH; c6++)
            s += Wout[o*DIM + h*CPH + c6] * attn_s[(b*HEADS + h)*36 + c6*CPH + d6];
        g_meff[e] = s;
    }
}

// fused: v = dw3x3(pwkv_hi) into smem tile, then out = Meff[b] * v.
// grid (WW/32, HH/8, BATCH), block 256 (8 warps x 6 channels / 6 oc).
__global__ __launch_bounds__(256, 2) void vout_kernel(const float* __restrict__ Wkv2,
                                                      float* __restrict__ out){
    extern __shared__ char smraw[];
    unsigned long long* wm = reinterpret_cast<unsigned long long*>(smraw);      // 48*48 u64
    float* v_s = reinterpret_cast<float*>(smraw + DIM*DIM*8);                   // 48*256 f32
    float* wv  = v_s + DIM*256;                                                 // 48*9 f32

    const int tid = threadIdx.x;
    const int b   = blockIdx.z;
    for (int t = tid; t < DIM*DIM; t += 256){
        float m = g_meff[b*DIM*DIM + t];
        wm[t] = pk2(m, m);
    }
    for (int t = tid; t < DIM*9; t += 256)
        wv[t] = Wkv2[(DIM + t/9)*27 + 9 + (t%9)];
    __syncthreads();

    const int lane = tid & 31;
    const int w    = tid >> 5;
    const int x0   = blockIdx.x*32;
    const int x    = x0 + lane;
    const int yb   = blockIdx.y*8;
    const int  xl = max(x-1, 0), xr = min(x+1, WW-1);
    const bool xm = (x > 0),     xp = (x < WW-1);

    const float* vbase = g_pwkv + (size_t)b*2*DIM*NPIX + (size_t)DIM*NPIX;
    #pragma unroll
    for (int c6 = 0; c6 < CPH; c6++){
        int c = w*CPH + c6;
        const float* p = vbase + (size_t)c*NPIX;
        float wr[9];
        #pragma unroll
        for (int t = 0; t < 9; t++) wr[t] = wv[c*9 + t];
        float r0[3], r1[3], r2[3];
        { bool yok = (yb-1 >= 0); row3(r0, p + (yok ? (yb-1) : 0)*WW, x, xl, xr, xm, xp, yok); }
        row3(r1, p + yb*WW, x, xl, xr, xm, xp, true);
        #pragma unroll
        for (int i = 0; i < 8; i++){
            int yy = yb + i + 1; bool yok = (yy < HH);
            row3(r2, p + (yok ? yy : 0)*WW, x, xl, xr, xm, xp, yok);
            float s; CONV9(s, wr, r0, r1, r2);
            v_s[c*256 + i*32 + lane] = s;
            r0[0]=r1[0]; r0[1]=r1[1]; r0[2]=r1[2];
            r1[0]=r2[0]; r1[1]=r2[1]; r1[2]=r2[2];
        }
    }
    __syncthreads();

    unsigned long long acc[CPH][4];
    #pragma unroll
    for (int j = 0; j < CPH; j++){
        acc[j][0]=0ull; acc[j][1]=0ull; acc[j][2]=0ull; acc[j][3]=0ull;
    }
    #pragma unroll 4
    for (int d = 0; d < DIM; d++){
        const float4* vp = reinterpret_cast<const float4*>(v_s + d*256);
        float4 a  = vp[lane];
        float4 bq = vp[lane + 32];
        unsigned long long a01 = pk2(a.x,  a.y ), a23 = pk2(a.z,  a.w );
        unsigned long long b01 = pk2(bq.x, bq.y), b23 = pk2(bq.z, bq.w);
        #pragma unroll
        for (int j = 0; j < CPH; j++){
            unsigned long long ww = wm[(w*CPH + j)*DIM + d];
            fma2(acc[j][0], a01, ww);
            fma2(acc[j][1], a23, ww);
            fma2(acc[j][2], b01, ww);
            fma2(acc[j][3], b23, ww);
        }
    }

    #pragma unroll
    for (int j = 0; j < CPH; j++){
        int oc = w*CPH + j;
        float* op = out + ((size_t)(b*DIM + oc))*NPIX;
        int px0 = 4*lane;
        int px1 = 128 + 4*lane;
        float2 l0 = unpk(acc[j][0]), h0 = unpk(acc[j][1]);
        float2 l1 = unpk(acc[j][2]), h1 = unpk(acc[j][3]);
        *reinterpret_cast<float4*>(op + (size_t)(yb + (px0>>5))*WW + x0 + (px0&31)) =
            make_float4(l0.x, l0.y, h0.x, h0.y);
        *reinterpret_cast<float4*>(op + (size_t)(yb + (px1>>5))*WW + x0 + (px1&31)) =
            make_float4(l1.x, l1.y, h1.x, h1.y);
    }
}

// ---------------- launch ----------------
extern "C" void kernel_launch(void* const* d_in, const int* in_sizes, int n_in,
                              void* d_out, int out_size){
    const float* img  = (const float*)d_in[0];
    const float* evs  = (const float*)d_in[1];
    const float* Wq1  = (const float*)d_in[2];
    const float* Wq2  = (const float*)d_in[3];
    const float* Wkv1 = (const float*)d_in[4];
    const float* Wkv2 = (const float*)d_in[5];
    const float* Wout = (const float*)d_in[6];
    const float* temp = (const float*)d_in[7];
    float* out = (float*)d_out;

    float *pwq, *pwkv;
    cudaGetSymbolAddress((void**)&pwq,  g_pwq);
    cudaGetSymbolAddress((void**)&pwkv, g_pwkv);

    size_t smem_pw   = (size_t)DIM*DIM*8 + (size_t)DIM*256*4;                   // 67584
    size_t smem_vout = (size_t)DIM*DIM*8 + (size_t)DIM*256*4 + (size_t)DIM*9*4; // 69312
    cudaFuncSetAttribute(pw8_kernel,  cudaFuncAttributeMaxDynamicSharedMemorySize, (int)smem_pw);
    cudaFuncSetAttribute(vout_kernel, cudaFuncAttributeMaxDynamicSharedMemorySize, (int)smem_vout);

    zero_acc_kernel<<<3, 256>>>();

    dim3 gpw(NPIX/256, BATCH);
    pw8_kernel<<<gpw, 256, smem_pw>>>(evs, Wq1,            pwq,                     DIM,   DIM);
    pw8_kernel<<<gpw, 256, smem_pw>>>(img, Wkv1,           pwkv,                    DIM, 2*DIM);
    pw8_kernel<<<gpw, 256, smem_pw>>>(img, Wkv1 + DIM*DIM, pwkv + (size_t)DIM*NPIX, DIM, 2*DIM);

    dim3 gqk(WW/32, HH/64, BATCH*HEADS);
    qk_gram_kernel<<<gqk, 256>>>(Wq2, Wkv2);

    attn_kernel<<<1, 256>>>(Wout, temp);

    dim3 gvo(WW/32, HH/8, BATCH);
    vout_kernel<<<gvo, 256, smem_vout>>>(Wkv2, out);
}